// round 7
// baseline (speedup 1.0000x reference)
#include <cuda_runtime.h>

// prediction: [32,4,512,512] f32 ; intervals: [32,4,64,2,2] i32 (x2 tensors)
// loss = 14.0 + sum w(comp,c,n)*(birth-death)^2
//   g = GOOD_comp[c]; w = -0.0625/g if n<g else +0.0625/(64-g)
// GOOD_0={1,2,1,3} -> nibbles 0x3121 ; GOOD_1={1,0,2,1} -> 0x1201
// g_accum rests at 14.0f so the final acquire-load is the answer directly.

#define NBC 128

__device__ float    g_accum = 14.0f;  // reset to 14.0f by last block each run
__device__ unsigned g_count = 0;      // atom.inc wraps at 128 -> replay-safe

__global__ void __launch_bounds__(32, 1)
bd_fused3_kernel(const float* __restrict__ pred,
                 const int*   __restrict__ iv0,
                 const int*   __restrict__ iv1,
                 float*       __restrict__ out)
{
    const int bc = blockIdx.x;     // b*4 + c
    const int c  = bc & 3;
    const int t  = threadIdx.x;    // 0..31

    // Each thread: 4 intervals -> 4 int4 coord loads + 8 gathers, all independent.
    const int4* v0 = reinterpret_cast<const int4*>(iv0) + bc * 64;
    const int4* v1 = reinterpret_cast<const int4*>(iv1) + bc * 64;
    int4 co[4];
    co[0] = v0[t];
    co[1] = v0[t + 32];
    co[2] = v1[t];
    co[3] = v1[t + 32];

    const float* p = pred + (size_t)bc * (512 * 512);
    const int g0 = (0x3121u >> (c * 4)) & 0xF;   // comp 0 good count
    const int g1 = (0x1201u >> (c * 4)) & 0xF;   // comp 1 good count

    float acc = 0.0f;
    #pragma unroll
    for (int j = 0; j < 4; j++) {
        const float birth = __ldg(p + ((co[j].x << 9) | co[j].y));
        const float death = __ldg(p + ((co[j].z << 9) | co[j].w));
        const int   g = (j < 2) ? g0 : g1;
        const int   n = t + ((j & 1) << 5);      // t or t+32
        const float w = (n < g) ? (-0.0625f / (float)g)
                                : ( 0.0625f / (float)(64 - g));
        const float d = birth - death;
        acc += w * d * d;
    }

    // Single-warp reduce: no smem, no __syncthreads.
    #pragma unroll
    for (int off = 16; off > 0; off >>= 1)
        acc += __shfl_down_sync(0xFFFFFFFFu, acc, off);

    if (t == 0) {
        asm volatile("red.release.gpu.global.add.f32 [%0], %1;"
                     :: "l"(&g_accum), "f"(acc) : "memory");
        unsigned old;
        asm volatile("atom.acq_rel.gpu.global.inc.u32 %0, [%1], %2;"
                     : "=r"(old) : "l"(&g_count), "r"(NBC - 1u) : "memory");
        if (old == NBC - 1u) {
            float total;
            asm volatile("ld.acquire.gpu.global.f32 %0, [%1];"
                         : "=f"(total) : "l"(&g_accum) : "memory");
            out[0] = total;                      // 14.0 already folded in
            asm volatile("st.global.f32 [%0], 0f41600000;"  // reset to 14.0f
                         :: "l"(&g_accum) : "memory");
        }
    }
}

extern "C" void kernel_launch(void* const* d_in, const int* in_sizes, int n_in,
                              void* d_out, int out_size)
{
    const float* pred = (const float*)d_in[0];
    const int*   iv0  = (const int*)d_in[1];
    const int*   iv1  = (const int*)d_in[2];
    bd_fused3_kernel<<<NBC, 32>>>(pred, iv0, iv1, (float*)d_out);
}

// round 8
// speedup vs baseline: 1.1586x; 1.1586x over previous
#include <cuda_runtime.h>

// prediction: [32,4,512,512] f32 ; intervals: [32,4,64,2,2] i32 (x2 tensors)
// loss = 14.0 + sum w(comp,c,n)*(birth-death)^2
//   g = GOOD_comp[c]; w = -0.0625/g if n<g else +0.0625/(64-g)
// GOOD_0={1,2,1,3} -> nibbles 0x3121 ; GOOD_1={1,0,2,1} -> 0x1201
// g_accum rests at 14.0f; last warp-leader's acquire-load IS the answer.

#define NBC   128
#define NARRV 512u   // 4 warp-leaders per block x 128 blocks

__device__ float    g_accum = 14.0f;  // reset to 14.0f by last arriver each run
__device__ unsigned g_count = 0;      // atom.inc wraps at NARRV -> replay-safe

__global__ void __launch_bounds__(128, 1)
bd_fused4_kernel(const float* __restrict__ pred,
                 const int*   __restrict__ iv0,
                 const int*   __restrict__ iv1,
                 float*       __restrict__ out)
{
    const int bc   = blockIdx.x;      // b*4 + c
    const int c    = bc & 3;
    const int tid  = threadIdx.x;     // 0..127
    const int comp = tid >> 6;        // warps 0,1 -> comp0 ; warps 2,3 -> comp1
    const int n    = tid & 63;

    const int* iv = comp ? iv1 : iv0;
    const int4 co = reinterpret_cast<const int4*>(iv)[bc * 64 + n];

    const float* p = pred + (size_t)bc * (512 * 512);
    const float birth = __ldg(p + ((co.x << 9) | co.y));
    const float death = __ldg(p + ((co.z << 9) | co.w));
    const float d = birth - death;

    const unsigned packed = comp ? 0x1201u : 0x3121u;
    const int g = (packed >> (c * 4)) & 0xF;
    const float w = (n < g) ? (-0.0625f / (float)g)
                            : ( 0.0625f / (float)(64 - g));
    float v = w * d * d;

    // Warp-level reduce only; each warp proceeds independently (no smem/BAR).
    #pragma unroll
    for (int off = 16; off > 0; off >>= 1)
        v += __shfl_down_sync(0xFFFFFFFFu, v, off);

    if ((tid & 31) == 0) {
        // Publish this warp's partial; release orders it before the inc below.
        asm volatile("red.release.gpu.global.add.f32 [%0], %1;"
                     :: "l"(&g_accum), "f"(v) : "memory");
        unsigned old;
        asm volatile("atom.acq_rel.gpu.global.inc.u32 %0, [%1], %2;"
                     : "=r"(old) : "l"(&g_count), "r"(NARRV - 1u) : "memory");
        if (old == NARRV - 1u) {
            float total;
            asm volatile("ld.acquire.gpu.global.f32 %0, [%1];"
                         : "=f"(total) : "l"(&g_accum) : "memory");
            out[0] = total;                                  // 14.0 folded in
            asm volatile("st.global.f32 [%0], 0f41600000;"   // reset to 14.0f
                         :: "l"(&g_accum) : "memory");
        }
    }
}

extern "C" void kernel_launch(void* const* d_in, const int* in_sizes, int n_in,
                              void* d_out, int out_size)
{
    const float* pred = (const float*)d_in[0];
    const int*   iv0  = (const int*)d_in[1];
    const int*   iv1  = (const int*)d_in[2];
    bd_fused4_kernel<<<NBC, 128>>>(pred, iv0, iv1, (float*)d_out);
}